// round 7
// baseline (speedup 1.0000x reference)
#include <cuda_runtime.h>
#include <cuda_bf16.h>
#include <math.h>

// Problem constants: B=4, MAX_T=200, MAX_U=101, VOCAB=1024
#define BB 4
#define TT 200
#define UU 101
#define UP 104                    // padded U stride (16-byte alignment for float4 loads)
#define VV 1024
#define DD (TT + UU - 1)          // 300 anti-diagonals
#define NCELLS (BB * TT * UU)     // 80800

// Scratch. Diagonal-major, padded, interleaved: g_probD[b][d*UP+u] = {blank_lp, label_lp}
__device__ float2 g_probD[BB * DD * UP];
__device__ float g_loss[BB];
__device__ int   g_valid[BB];
__device__ unsigned g_ticket;     // zero-init; last block resets after use

// ---------------------------------------------------------------------------
// Per-warp helpers (all 32 lanes participate). int64 labels < 1024 => every
// odd int32 word is 0 (P[false positive] ~ 1024^-64).
// ---------------------------------------------------------------------------
__device__ __forceinline__ int warp_detect_is64(const int* __restrict__ labels_i32)
{
    const int lane = threadIdx.x & 31;
    int ok = 1;
#pragma unroll
    for (int i = 1 + 2 * lane; i < 256; i += 64)
        ok &= (labels_i32[i] == 0);
    return __all_sync(0xffffffffu, ok);
}

__device__ __forceinline__ int warp_input_len(const int* __restrict__ attention_mask, int b)
{
    const int lane = threadIdx.x & 31;
    int acc = 0;
#pragma unroll
    for (int k = lane; k < TT; k += 32)
        acc += attention_mask[b * TT + k];
#pragma unroll
    for (int off = 16; off > 0; off >>= 1)
        acc += __shfl_xor_sync(0xffffffffu, acc, off);
    return acc < 1 ? 1 : (acc > TT ? TT : acc);
}

__device__ __forceinline__ int load_int(const void* p, int idx, int is64)
{
    return is64 ? (int)((const long long*)p)[idx] : ((const int*)p)[idx];
}

// ---------------------------------------------------------------------------
// Kernel 1: streaming logsumexp over V=1024 per live cell; one warp/cell.
// Dead cells (u > label_len[b] || t >= input_len[b]) exit before any logits
// loads. Writes diagonal-major padded layout at the CONSUMER position:
//   blank of (t,u)    -> g_probD[b][(t+u)*UP + u].x
//   label_lp of (t,u) -> g_probD[b][(t+u+1)*UP + (u+1)].y
// ---------------------------------------------------------------------------
__global__ void __launch_bounds__(256)
lse_kernel(const float* __restrict__ logits,
           const void* __restrict__ labels,
           const void* __restrict__ label_lengths,
           const int* __restrict__ attention_mask)
{
    const int warp = threadIdx.x >> 5;
    const int lane = threadIdx.x & 31;
    const int cell = blockIdx.x * 8 + warp;
    if (cell >= NCELLS) return;

    const int b = cell / (TT * UU);
    const int rem = cell - b * (TT * UU);
    const int t = rem / UU;
    const int u = rem - t * UU;

    const int is64 = warp_detect_is64((const int*)labels);
    int ll = load_int(label_lengths, b, is64);
    ll = ll < 0 ? 0 : (ll > UU - 1 ? UU - 1 : ll);
    const int il = warp_input_len(attention_mask, b);
    if (u > ll || t >= il) return;          // dead cell: skip all logits loads

    const float* base = logits + (size_t)cell * VV;
    const float4* p = (const float4*)base;

    float s = 0.f;
    float first = 0.f;   // lane 0, i=0, .x == blank logit
#pragma unroll
    for (int i = 0; i < 8; i++) {
        float4 v = p[i * 32 + lane];
        if (i == 0) first = v.x;
        s += __expf(v.x) + __expf(v.y) + __expf(v.z) + __expf(v.w);
    }
#pragma unroll
    for (int off = 16; off > 0; off >>= 1)
        s += __shfl_xor_sync(0xffffffffu, s, off);

    const float lse = __logf(s);

    if (lane == 0) {
        float* pd = (float*)g_probD;
        const int base_b = b * (DD * UP);
        pd[2 * (base_b + (t + u) * UP + u)] = first - lse;          // .x blank
        if (u < ll) {
            int lab = load_int(labels, b * (UU - 1) + u, is64);
            lab = lab < 0 ? 0 : (lab > VV - 1 ? VV - 1 : lab);
            const float lab_logit = __ldg(base + lab);
            pd[2 * (base_b + (t + u + 1) * UP + (u + 1)) + 1] = lab_logit - lse;  // .y
        }
    }
}

// ---------------------------------------------------------------------------
// Kernel 2: alpha wavefront, ONE WARP per sample, 4 u-values per lane.
// All parents of diagonal d live on diagonal d-1, so each lane needs only its
// own 4 registers plus ONE shfl_up per diagonal (alpha[d-1][4*lane-1]).
// The 4 logadds per lane are independent. No smem, no barriers, no spins.
// 3-deep register prefetch of the float2 prob pairs (2 aligned float4 / diag).
// ---------------------------------------------------------------------------
__device__ __forceinline__ float logadd_(float a, float b) {
    float mx = fmaxf(a, b);
    float mn = fminf(a, b);
    return mx + __logf(1.f + __expf(mn - mx));
}

// alpha(d,u) from top=alpha(d-1,u), left=alpha(d-1,u-1).
// Garbage in inactive cells never reaches the active cone (see analysis).
__device__ __forceinline__ float stepcell(float top, float left,
                                          float blank, float label,
                                          int t, int u)
{
    const float viaB = top + blank;
    const float viaL = left + label;
    if (u == 0) return (t == 0) ? blank : viaB;   // blank-only column / origin
    if (t == 0) return viaL;                      // label-only row
    return logadd_(viaB, viaL);
}

__global__ void __launch_bounds__(32)
alpha_kernel(const void* __restrict__ labels,
             const void* __restrict__ label_lengths,
             const int* __restrict__ attention_mask,
             float* __restrict__ out)
{
    const int b = blockIdx.x;
    const int lane = threadIdx.x;

    const int is64 = warp_detect_is64((const int*)labels);
    const int il = warp_input_len(attention_mask, b);
    int ll = load_int(label_lengths, b, is64);
    ll = ll < 0 ? 0 : (ll > UU - 1 ? UU - 1 : ll);
    const int target_d = (il - 1) + ll;

    const float2* pD = g_probD + b * (DD * UP);
    const int u0 = lane * 4;                 // lanes 0..25 cover u = 0..103

    // 3-deep prefetch ring: pf[k] holds diagonal (d+k) when processing d.
    float4 pf[3][2];
#pragma unroll
    for (int k = 0; k < 3; k++) {
        const float4* p = (const float4*)(pD + k * UP + u0);
        pf[k][0] = p[0];
        pf[k][1] = p[1];
    }

    float a0 = 0.f, a1 = 0.f, a2 = 0.f, a3 = 0.f;   // alpha(d-1, u0..u0+3)
    float result = 0.f;
    int slot = 0;

    for (int d = 0; d <= target_d; d++) {
        const float4 cA = pf[slot][0];   // (blank,label)@u0, (blank,label)@u0+1
        const float4 cB = pf[slot][1];   // @u0+2, @u0+3

        // prefetch diagonal d+3 into the slot we just consumed
        const int dn = d + 3;
        if (dn <= target_d) {
            const float4* p = (const float4*)(pD + dn * UP + u0);
            pf[slot][0] = p[0];
            pf[slot][1] = p[1];
        }
        slot = (slot == 2) ? 0 : slot + 1;

        // boundary: alpha(d-1, u0-1) from left lane (lockstep, no sync needed)
        const float left0 = __shfl_up_sync(0xffffffffu, a3, 1);

        const int t0 = d - u0;
        const float n0 = stepcell(a0, left0, cA.x, cA.y, t0,     u0);
        const float n1 = stepcell(a1, a0,    cA.z, cA.w, t0 - 1, u0 + 1);
        const float n2 = stepcell(a2, a1,    cB.x, cB.y, t0 - 2, u0 + 2);
        const float n3 = stepcell(a3, a2,    cB.z, cB.w, t0 - 3, u0 + 3);
        a0 = n0; a1 = n1; a2 = n2; a3 = n3;

        if (d == target_d && u0 <= ll && ll < u0 + 4) {
            result = (ll == u0) ? n0 : (ll == u0 + 1) ? n1
                   : (ll == u0 + 2) ? n2 : n3;
            const bool valid = (il > 0) && (ll > 0);
            g_loss[b] = valid ? -result : 0.f;
            g_valid[b] = valid ? 1 : 0;
        }
    }

    // Fused mean reduction: last warp to arrive writes the scalar.
    if (lane == 0) {
        __threadfence();
        const unsigned tk = atomicAdd(&g_ticket, 1u);
        if (tk == BB - 1) {
            __threadfence();
            float s = 0.f;
            int nv = 0;
#pragma unroll
            for (int i = 0; i < BB; i++) { s += g_loss[i]; nv += g_valid[i]; }
            out[0] = s / (float)(nv > 0 ? nv : 1);
            g_ticket = 0;                  // reset for next graph replay
            __threadfence();
        }
    }
}

extern "C" void kernel_launch(void* const* d_in, const int* in_sizes, int n_in,
                              void* d_out, int out_size)
{
    const float* logits = (const float*)d_in[0];
    const void* labels = d_in[1];
    const void* label_lengths = d_in[2];
    const int* attention_mask = (const int*)d_in[3];
    float* out = (float*)d_out;

    lse_kernel<<<(NCELLS + 7) / 8, 256>>>(logits, labels, label_lengths, attention_mask);
    alpha_kernel<<<BB, 32>>>(labels, label_lengths, attention_mask, out);
}

// round 8
// speedup vs baseline: 1.2182x; 1.2182x over previous
#include <cuda_runtime.h>
#include <cuda_bf16.h>
#include <math.h>

// Problem constants: B=4, MAX_T=200, MAX_U=101, VOCAB=1024
#define BB 4
#define TT 200
#define UU 101
#define UP 104                    // padded U stride (16B alignment for float4)
#define VV 1024
#define DD (TT + UU - 1)          // 300 anti-diagonals
#define NCELLS (BB * TT * UU)     // 80800

// Scratch. Diagonal-major, padded, interleaved: g_probD[b][d*UP+u] = {blank_lp, label_lp}
__device__ float2 g_probD[BB * DD * UP];
__device__ float g_loss[BB];
__device__ int   g_valid[BB];
__device__ unsigned g_ticket;     // zero-init; last block resets after use

// ---------------------------------------------------------------------------
// Per-warp helpers (all 32 lanes participate). int64 labels < 1024 => every
// odd int32 word is 0 (P[false positive] ~ 1024^-64).
// ---------------------------------------------------------------------------
__device__ __forceinline__ int warp_detect_is64(const int* __restrict__ labels_i32)
{
    const int lane = threadIdx.x & 31;
    int ok = 1;
#pragma unroll
    for (int i = 1 + 2 * lane; i < 256; i += 64)
        ok &= (labels_i32[i] == 0);
    return __all_sync(0xffffffffu, ok);
}

__device__ __forceinline__ int warp_input_len(const int* __restrict__ attention_mask, int b)
{
    const int lane = threadIdx.x & 31;
    int acc = 0;
#pragma unroll
    for (int k = lane; k < TT; k += 32)
        acc += attention_mask[b * TT + k];
#pragma unroll
    for (int off = 16; off > 0; off >>= 1)
        acc += __shfl_xor_sync(0xffffffffu, acc, off);
    return acc < 1 ? 1 : (acc > TT ? TT : acc);
}

__device__ __forceinline__ int load_int(const void* p, int idx, int is64)
{
    return is64 ? (int)((const long long*)p)[idx] : ((const int*)p)[idx];
}

// ---------------------------------------------------------------------------
// Kernel 1: streaming logsumexp over V=1024 per live cell; one warp/cell.
// Dead cells (u > label_len[b] || t >= input_len[b]) exit before any logits
// loads. Writes diagonal-major padded layout at the CONSUMER position:
//   blank of (t,u)    -> g_probD[b][(t+u)*UP + u].x
//   label_lp of (t,u) -> g_probD[b][(t+u+1)*UP + (u+1)].y
// ---------------------------------------------------------------------------
__global__ void __launch_bounds__(256)
lse_kernel(const float* __restrict__ logits,
           const void* __restrict__ labels,
           const void* __restrict__ label_lengths,
           const int* __restrict__ attention_mask)
{
    const int warp = threadIdx.x >> 5;
    const int lane = threadIdx.x & 31;
    const int cell = blockIdx.x * 8 + warp;
    if (cell >= NCELLS) return;

    const int b = cell / (TT * UU);
    const int rem = cell - b * (TT * UU);
    const int t = rem / UU;
    const int u = rem - t * UU;

    const int is64 = warp_detect_is64((const int*)labels);
    int ll = load_int(label_lengths, b, is64);
    ll = ll < 0 ? 0 : (ll > UU - 1 ? UU - 1 : ll);
    const int il = warp_input_len(attention_mask, b);
    if (u > ll || t >= il) return;          // dead cell: skip all logits loads

    const float* base = logits + (size_t)cell * VV;
    const float4* p = (const float4*)base;

    float s = 0.f;
    float first = 0.f;   // lane 0, i=0, .x == blank logit
#pragma unroll
    for (int i = 0; i < 8; i++) {
        float4 v = p[i * 32 + lane];
        if (i == 0) first = v.x;
        s += __expf(v.x) + __expf(v.y) + __expf(v.z) + __expf(v.w);
    }
#pragma unroll
    for (int off = 16; off > 0; off >>= 1)
        s += __shfl_xor_sync(0xffffffffu, s, off);

    const float lse = __logf(s);

    if (lane == 0) {
        float* pd = (float*)g_probD;
        const int base_b = b * (DD * UP);
        pd[2 * (base_b + (t + u) * UP + u)] = first - lse;          // .x blank
        if (u < ll) {
            int lab = load_int(labels, b * (UU - 1) + u, is64);
            lab = lab < 0 ? 0 : (lab > VV - 1 ? VV - 1 : lab);
            const float lab_logit = __ldg(base + lab);
            pd[2 * (base_b + (t + u + 1) * UP + (u + 1)) + 1] = lab_logit - lse;  // .y
        }
    }
}

// ---------------------------------------------------------------------------
// Kernel 2: alpha wavefront, ONE WARP per sample, 4 u-values per lane.
// All parents of diagonal d live on diagonal d-1: each lane needs only its 4
// registers plus ONE shfl_up (alpha[d-1][4*lane-1]). No smem/barriers/spins.
// R7 FIX: prefetch ring indices are now COMPILE-TIME (loop unrolled x3 with
// named float4 pairs) so nothing spills to local memory.
// ---------------------------------------------------------------------------
__device__ __forceinline__ float logadd_(float a, float b) {
    float mx = fmaxf(a, b);
    float mn = fminf(a, b);
    return mx + __logf(1.f + __expf(mn - mx));
}

// alpha(d,u) from top=alpha(d-1,u), left=alpha(d-1,u-1).
// Garbage in inactive cells never reaches the active cone.
__device__ __forceinline__ float stepcell(float top, float left,
                                          float blank, float label,
                                          int t, int u)
{
    const float viaB = top + blank;
    const float viaL = left + label;
    if (u == 0) return (t == 0) ? blank : viaB;   // blank-only column / origin
    if (t == 0) return viaL;                      // label-only row
    return logadd_(viaB, viaL);
}

__global__ void __launch_bounds__(32)
alpha_kernel(const void* __restrict__ labels,
             const void* __restrict__ label_lengths,
             const int* __restrict__ attention_mask,
             float* __restrict__ out)
{
    const int b = blockIdx.x;
    const int lane = threadIdx.x;

    const int is64 = warp_detect_is64((const int*)labels);
    const int il = warp_input_len(attention_mask, b);
    int ll = load_int(label_lengths, b, is64);
    ll = ll < 0 ? 0 : (ll > UU - 1 ? UU - 1 : ll);
    const int target_d = (il - 1) + ll;

    const float2* pD = g_probD + b * (DD * UP);
    const int u0 = lane * 4;                 // lanes 0..25 cover u = 0..103

    // 3-deep prefetch with NAMED registers (no dynamic indexing).
    float4 pA0, pB0, pA1, pB1, pA2, pB2;
    {
        const float4* p0 = (const float4*)(pD + 0 * UP + u0);
        const float4* p1 = (const float4*)(pD + 1 * UP + u0);
        const float4* p2 = (const float4*)(pD + 2 * UP + u0);
        pA0 = p0[0]; pB0 = p0[1];
        pA1 = p1[0]; pB1 = p1[1];
        pA2 = p2[0]; pB2 = p2[1];
    }

    float a0 = 0.f, a1 = 0.f, a2 = 0.f, a3 = 0.f;   // alpha(d-1, u0..u0+3)

    // One unrolled step; DCUR <= target_d is warp-uniform (all inputs uniform),
    // so the shfl inside executes convergently.
#define ALPHA_STEP(PA, PB, DCUR)                                              \
    if ((DCUR) <= target_d) {                                                 \
        const float4 cA = PA, cB = PB;                                        \
        const int dn = (DCUR) + 3;                                            \
        if (dn <= target_d) {                                                 \
            const float4* pp = (const float4*)(pD + dn * UP + u0);            \
            PA = pp[0]; PB = pp[1];                                           \
        }                                                                     \
        const float left0 = __shfl_up_sync(0xffffffffu, a3, 1);               \
        const int t0 = (DCUR) - u0;                                           \
        const float n0 = stepcell(a0, left0, cA.x, cA.y, t0,     u0);         \
        const float n1 = stepcell(a1, a0,    cA.z, cA.w, t0 - 1, u0 + 1);     \
        const float n2 = stepcell(a2, a1,    cB.x, cB.y, t0 - 2, u0 + 2);     \
        const float n3 = stepcell(a3, a2,    cB.z, cB.w, t0 - 3, u0 + 3);     \
        a0 = n0; a1 = n1; a2 = n2; a3 = n3;                                   \
        if ((DCUR) == target_d && u0 <= ll && ll < u0 + 4) {                  \
            const float r = (ll == u0) ? n0 : (ll == u0 + 1) ? n1             \
                          : (ll == u0 + 2) ? n2 : n3;                         \
            const bool valid = (il > 0) && (ll > 0);                          \
            g_loss[b] = valid ? -r : 0.f;                                     \
            g_valid[b] = valid ? 1 : 0;                                       \
        }                                                                     \
    }

    for (int d = 0; d <= target_d; d += 3) {
        ALPHA_STEP(pA0, pB0, d)
        ALPHA_STEP(pA1, pB1, d + 1)
        ALPHA_STEP(pA2, pB2, d + 2)
    }
#undef ALPHA_STEP

    // Fused mean reduction: last warp to arrive writes the scalar.
    if (lane == 0) {
        __threadfence();
        const unsigned tk = atomicAdd(&g_ticket, 1u);
        if (tk == BB - 1) {
            __threadfence();
            float s = 0.f;
            int nv = 0;
#pragma unroll
            for (int i = 0; i < BB; i++) { s += g_loss[i]; nv += g_valid[i]; }
            out[0] = s / (float)(nv > 0 ? nv : 1);
            g_ticket = 0;                  // reset for next graph replay
            __threadfence();
        }
    }
}

extern "C" void kernel_launch(void* const* d_in, const int* in_sizes, int n_in,
                              void* d_out, int out_size)
{
    const float* logits = (const float*)d_in[0];
    const void* labels = d_in[1];
    const void* label_lengths = d_in[2];
    const int* attention_mask = (const int*)d_in[3];
    float* out = (float*)d_out;

    lse_kernel<<<(NCELLS + 7) / 8, 256>>>(logits, labels, label_lengths, attention_mask);
    alpha_kernel<<<BB, 32>>>(labels, label_lengths, attention_mask, out);
}

// round 9
// speedup vs baseline: 1.9635x; 1.6118x over previous
#include <cuda_runtime.h>
#include <cuda_bf16.h>
#include <math.h>

// Problem constants: B=4, MAX_T=200, MAX_U=101, VOCAB=1024
#define BB 4
#define TT 200
#define UU 101
#define UP 104                    // padded U stride (16B alignment for float4)
#define VV 1024
#define DD (TT + UU - 1)          // 300 anti-diagonals
#define NCELLS (BB * TT * UU)     // 80800

// Scratch. Diagonal-major, padded, interleaved: g_probD[b][d*UP+u] = {blank_lp, label_lp}
__device__ float2 g_probD[BB * DD * UP];
__device__ float g_loss[BB];
__device__ int   g_valid[BB];
__device__ unsigned g_ticket;     // zero-init; last block resets after use

// ---------------------------------------------------------------------------
// Per-warp helpers (all 32 lanes participate). int64 labels < 1024 => every
// odd int32 word is 0 (P[false positive] ~ 1024^-64).
// ---------------------------------------------------------------------------
__device__ __forceinline__ int warp_detect_is64(const int* __restrict__ labels_i32)
{
    const int lane = threadIdx.x & 31;
    int ok = 1;
#pragma unroll
    for (int i = 1 + 2 * lane; i < 256; i += 64)
        ok &= (labels_i32[i] == 0);
    return __all_sync(0xffffffffu, ok);
}

__device__ __forceinline__ int warp_input_len(const int* __restrict__ attention_mask, int b)
{
    const int lane = threadIdx.x & 31;
    int acc = 0;
#pragma unroll
    for (int k = lane; k < TT; k += 32)
        acc += attention_mask[b * TT + k];
#pragma unroll
    for (int off = 16; off > 0; off >>= 1)
        acc += __shfl_xor_sync(0xffffffffu, acc, off);
    return acc < 1 ? 1 : (acc > TT ? TT : acc);
}

__device__ __forceinline__ int load_int(const void* p, int idx, int is64)
{
    return is64 ? (int)((const long long*)p)[idx] : ((const int*)p)[idx];
}

// ---------------------------------------------------------------------------
// Kernel 1: streaming logsumexp over V=1024 per live cell; one warp/cell.
// Logits are loaded with __ldcs (evict-first): zero reuse, and critically this
// keeps the freshly written g_probD lines resident in L2 for alpha_kernel.
// Dead cells (u > label_len[b] || t >= input_len[b]) exit before any loads.
// Writes diagonal-major padded layout at the CONSUMER position:
//   blank of (t,u)    -> g_probD[b][(t+u)*UP + u].x
//   label_lp of (t,u) -> g_probD[b][(t+u+1)*UP + (u+1)].y
// ---------------------------------------------------------------------------
__global__ void __launch_bounds__(256)
lse_kernel(const float* __restrict__ logits,
           const void* __restrict__ labels,
           const void* __restrict__ label_lengths,
           const int* __restrict__ attention_mask)
{
    const int warp = threadIdx.x >> 5;
    const int lane = threadIdx.x & 31;
    const int cell = blockIdx.x * 8 + warp;
    if (cell >= NCELLS) return;

    const int b = cell / (TT * UU);
    const int rem = cell - b * (TT * UU);
    const int t = rem / UU;
    const int u = rem - t * UU;

    const int is64 = warp_detect_is64((const int*)labels);
    int ll = load_int(label_lengths, b, is64);
    ll = ll < 0 ? 0 : (ll > UU - 1 ? UU - 1 : ll);
    const int il = warp_input_len(attention_mask, b);
    if (u > ll || t >= il) return;          // dead cell: skip all logits loads

    const float* base = logits + (size_t)cell * VV;
    const float4* p = (const float4*)base;

    float s = 0.f;
    float first = 0.f;   // lane 0, i=0, .x == blank logit
#pragma unroll
    for (int i = 0; i < 8; i++) {
        float4 v = __ldcs(p + i * 32 + lane);      // streaming: don't pollute L2
        if (i == 0) first = v.x;
        s += __expf(v.x) + __expf(v.y) + __expf(v.z) + __expf(v.w);
    }
#pragma unroll
    for (int off = 16; off > 0; off >>= 1)
        s += __shfl_xor_sync(0xffffffffu, s, off);

    const float lse = __logf(s);

    if (lane == 0) {
        float* pd = (float*)g_probD;
        const int base_b = b * (DD * UP);
        pd[2 * (base_b + (t + u) * UP + u)] = first - lse;          // .x blank
        if (u < ll) {
            int lab = load_int(labels, b * (UU - 1) + u, is64);
            lab = lab < 0 ? 0 : (lab > VV - 1 ? VV - 1 : lab);
            const float lab_logit = __ldcs(base + lab);
            pd[2 * (base_b + (t + u + 1) * UP + (u + 1)) + 1] = lab_logit - lse;  // .y
        }
    }
}

// ---------------------------------------------------------------------------
// Kernel 2: alpha wavefront, ONE WARP per sample, 4 u-values per lane.
// All parents of diagonal d live on diagonal d-1: each lane needs only its 4
// registers plus ONE shfl_up (alpha[d-1][4*lane-1]). No smem/barriers/spins.
// 6-deep NAMED-register prefetch (loop unrolled x6) covers L2 hit latency.
// Only lanes 0..25 load (u0 <= 100); higher lanes' garbage never reaches the
// active cone (garbage propagates monotonically in u and t).
// ---------------------------------------------------------------------------
__device__ __forceinline__ float logadd_(float a, float b) {
    float mx = fmaxf(a, b);
    float mn = fminf(a, b);
    return mx + __logf(1.f + __expf(mn - mx));
}

// alpha(d,u) from top=alpha(d-1,u), left=alpha(d-1,u-1).
__device__ __forceinline__ float stepcell(float top, float left,
                                          float blank, float label,
                                          int t, int u)
{
    const float viaB = top + blank;
    const float viaL = left + label;
    if (u == 0) return (t == 0) ? blank : viaB;   // blank-only column / origin
    if (t == 0) return viaL;                      // label-only row
    return logadd_(viaB, viaL);
}

__global__ void __launch_bounds__(32)
alpha_kernel(const void* __restrict__ labels,
             const void* __restrict__ label_lengths,
             const int* __restrict__ attention_mask,
             float* __restrict__ out)
{
    const int b = blockIdx.x;
    const int lane = threadIdx.x;

    const int is64 = warp_detect_is64((const int*)labels);
    const int il = warp_input_len(attention_mask, b);
    int ll = load_int(label_lengths, b, is64);
    ll = ll < 0 ? 0 : (ll > UU - 1 ? UU - 1 : ll);
    const int target_d = (il - 1) + ll;

    const float2* pD = g_probD + b * (DD * UP);
    const int u0 = lane * 4;                 // lanes 0..25 cover u = 0..103
    const bool lload = (u0 < UP);            // lanes 26+ never load (OOB guard)

    // 6-deep prefetch with NAMED registers (no dynamic indexing -> no spill).
    float4 pA0, pB0, pA1, pB1, pA2, pB2, pA3, pB3, pA4, pB4, pA5, pB5;
#define PF_INIT(PA, PB, K)                                                    \
    if (lload) {                                                              \
        const float4* p_ = (const float4*)(pD + (K) * UP + u0);               \
        PA = p_[0]; PB = p_[1];                                               \
    } else { PA = make_float4(0,0,0,0); PB = make_float4(0,0,0,0); }
    PF_INIT(pA0, pB0, 0) PF_INIT(pA1, pB1, 1) PF_INIT(pA2, pB2, 2)
    PF_INIT(pA3, pB3, 3) PF_INIT(pA4, pB4, 4) PF_INIT(pA5, pB5, 5)
#undef PF_INIT

    float a0 = 0.f, a1 = 0.f, a2 = 0.f, a3 = 0.f;   // alpha(d-1, u0..u0+3)

    // DCUR <= target_d is warp-uniform, so the shfl executes convergently.
#define ALPHA_STEP(PA, PB, DCUR)                                              \
    if ((DCUR) <= target_d) {                                                 \
        const float4 cA = PA, cB = PB;                                        \
        const int dn = (DCUR) + 6;                                            \
        if (lload && dn <= target_d) {                                        \
            const float4* pp = (const float4*)(pD + dn * UP + u0);            \
            PA = pp[0]; PB = pp[1];                                           \
        }                                                                     \
        const float left0 = __shfl_up_sync(0xffffffffu, a3, 1);               \
        const int t0 = (DCUR) - u0;                                           \
        const float n0 = stepcell(a0, left0, cA.x, cA.y, t0,     u0);         \
        const float n1 = stepcell(a1, a0,    cA.z, cA.w, t0 - 1, u0 + 1);     \
        const float n2 = stepcell(a2, a1,    cB.x, cB.y, t0 - 2, u0 + 2);     \
        const float n3 = stepcell(a3, a2,    cB.z, cB.w, t0 - 3, u0 + 3);     \
        a0 = n0; a1 = n1; a2 = n2; a3 = n3;                                   \
        if ((DCUR) == target_d && u0 <= ll && ll < u0 + 4) {                  \
            const float r = (ll == u0) ? n0 : (ll == u0 + 1) ? n1             \
                          : (ll == u0 + 2) ? n2 : n3;                         \
            const bool valid = (il > 0) && (ll > 0);                          \
            g_loss[b] = valid ? -r : 0.f;                                     \
            g_valid[b] = valid ? 1 : 0;                                       \
        }                                                                     \
    }

    for (int d = 0; d <= target_d; d += 6) {
        ALPHA_STEP(pA0, pB0, d)
        ALPHA_STEP(pA1, pB1, d + 1)
        ALPHA_STEP(pA2, pB2, d + 2)
        ALPHA_STEP(pA3, pB3, d + 3)
        ALPHA_STEP(pA4, pB4, d + 4)
        ALPHA_STEP(pA5, pB5, d + 5)
    }
#undef ALPHA_STEP

    // Fused mean reduction: last warp to arrive writes the scalar.
    if (lane == 0) {
        __threadfence();
        const unsigned tk = atomicAdd(&g_ticket, 1u);
        if (tk == BB - 1) {
            __threadfence();
            float s = 0.f;
            int nv = 0;
#pragma unroll
            for (int i = 0; i < BB; i++) { s += g_loss[i]; nv += g_valid[i]; }
            out[0] = s / (float)(nv > 0 ? nv : 1);
            g_ticket = 0;                  // reset for next graph replay
            __threadfence();
        }
    }
}

extern "C" void kernel_launch(void* const* d_in, const int* in_sizes, int n_in,
                              void* d_out, int out_size)
{
    const float* logits = (const float*)d_in[0];
    const void* labels = d_in[1];
    const void* label_lengths = d_in[2];
    const int* attention_mask = (const int*)d_in[3];
    float* out = (float*)d_out;

    lse_kernel<<<(NCELLS + 7) / 8, 256>>>(logits, labels, label_lengths, attention_mask);
    alpha_kernel<<<BB, 32>>>(labels, label_lengths, attention_mask, out);
}

// round 10
// speedup vs baseline: 2.0037x; 1.0205x over previous
#include <cuda_runtime.h>
#include <cuda_bf16.h>
#include <math.h>

// Problem constants: B=4, MAX_T=200, MAX_U=101, VOCAB=1024
#define BB 4
#define TT 200
#define UU 101
#define UP 104                    // padded U stride (16B alignment for float4)
#define VV 1024
#define DD (TT + UU - 1)          // 300 anti-diagonals
#define NCELLS (BB * TT * UU)     // 80800

// Scratch. Diagonal-major, padded, interleaved: g_probD[b][d*UP+u] = {blank_lp, label_lp}
__device__ float2 g_probD[BB * DD * UP];
__device__ float g_loss[BB];
__device__ int   g_valid[BB];
__device__ unsigned g_ticket;     // zero-init; last block resets after use

// ---------------------------------------------------------------------------
// Per-warp helpers (all 32 lanes participate). int64 labels < 1024 => every
// odd int32 word is 0 (P[false positive] ~ 1024^-64).
// ---------------------------------------------------------------------------
__device__ __forceinline__ int warp_detect_is64(const int* __restrict__ labels_i32)
{
    const int lane = threadIdx.x & 31;
    int ok = 1;
#pragma unroll
    for (int i = 1 + 2 * lane; i < 256; i += 64)
        ok &= (labels_i32[i] == 0);
    return __all_sync(0xffffffffu, ok);
}

__device__ __forceinline__ int warp_input_len(const int* __restrict__ attention_mask, int b)
{
    const int lane = threadIdx.x & 31;
    int acc = 0;
#pragma unroll
    for (int k = lane; k < TT; k += 32)
        acc += attention_mask[b * TT + k];
#pragma unroll
    for (int off = 16; off > 0; off >>= 1)
        acc += __shfl_xor_sync(0xffffffffu, acc, off);
    return acc < 1 ? 1 : (acc > TT ? TT : acc);
}

__device__ __forceinline__ int load_int(const void* p, int idx, int is64)
{
    return is64 ? (int)((const long long*)p)[idx] : ((const int*)p)[idx];
}

// ---------------------------------------------------------------------------
// Kernel 1: streaming logsumexp over V=1024 per live cell; one warp/cell.
// Logits loaded with __ldcs (evict-first; zero reuse). Dead cells exit before
// any logits loads. Writes diagonal-major padded layout at CONSUMER position:
//   blank of (t,u)    -> g_probD[b][(t+u)*UP + u].x
//   label_lp of (t,u) -> g_probD[b][(t+u+1)*UP + (u+1)].y
// ---------------------------------------------------------------------------
__global__ void __launch_bounds__(256)
lse_kernel(const float* __restrict__ logits,
           const void* __restrict__ labels,
           const void* __restrict__ label_lengths,
           const int* __restrict__ attention_mask)
{
    const int warp = threadIdx.x >> 5;
    const int lane = threadIdx.x & 31;
    const int cell = blockIdx.x * 8 + warp;
    if (cell >= NCELLS) return;

    const int b = cell / (TT * UU);
    const int rem = cell - b * (TT * UU);
    const int t = rem / UU;
    const int u = rem - t * UU;

    const int is64 = warp_detect_is64((const int*)labels);
    int ll = load_int(label_lengths, b, is64);
    ll = ll < 0 ? 0 : (ll > UU - 1 ? UU - 1 : ll);
    const int il = warp_input_len(attention_mask, b);
    if (u > ll || t >= il) return;          // dead cell: skip all logits loads

    const float* base = logits + (size_t)cell * VV;
    const float4* p = (const float4*)base;

    float s = 0.f;
    float first = 0.f;   // lane 0, i=0, .x == blank logit
#pragma unroll
    for (int i = 0; i < 8; i++) {
        float4 v = __ldcs(p + i * 32 + lane);      // streaming: don't pollute L2
        if (i == 0) first = v.x;
        s += __expf(v.x) + __expf(v.y) + __expf(v.z) + __expf(v.w);
    }
#pragma unroll
    for (int off = 16; off > 0; off >>= 1)
        s += __shfl_xor_sync(0xffffffffu, s, off);

    const float lse = __logf(s);

    if (lane == 0) {
        float* pd = (float*)g_probD;
        const int base_b = b * (DD * UP);
        pd[2 * (base_b + (t + u) * UP + u)] = first - lse;          // .x blank
        if (u < ll) {
            int lab = load_int(labels, b * (UU - 1) + u, is64);
            lab = lab < 0 ? 0 : (lab > VV - 1 ? VV - 1 : lab);
            const float lab_logit = __ldcs(base + lab);
            pd[2 * (base_b + (t + u + 1) * UP + (u + 1)) + 1] = lab_logit - lse;  // .y
        }
    }
}

// ---------------------------------------------------------------------------
// Kernel 2: alpha wavefront, ONE WARP per sample, 4 u-values per lane.
// All parents of diagonal d live on diagonal d-1: each lane needs only its 4
// registers plus ONE shfl_up. No smem/barriers/spins.
// 12-deep NAMED-register prefetch: coverage 12 x ~60cyc chain ~ 720 cyc >
// DRAM latency (577), so the recurrence runs at the logadd-chain floor even
// when probD misses L2. All ring indices compile-time (no local-mem spill).
// ---------------------------------------------------------------------------
__device__ __forceinline__ float logadd_(float a, float b) {
    float mx = fmaxf(a, b);
    float mn = fminf(a, b);
    return mx + __logf(1.f + __expf(mn - mx));
}

// alpha(d,u) from top=alpha(d-1,u), left=alpha(d-1,u-1).
__device__ __forceinline__ float stepcell(float top, float left,
                                          float blank, float label,
                                          int t, int u)
{
    const float viaB = top + blank;
    const float viaL = left + label;
    if (u == 0) return (t == 0) ? blank : viaB;   // blank-only column / origin
    if (t == 0) return viaL;                      // label-only row
    return logadd_(viaB, viaL);
}

__global__ void __launch_bounds__(32)
alpha_kernel(const void* __restrict__ labels,
             const void* __restrict__ label_lengths,
             const int* __restrict__ attention_mask,
             float* __restrict__ out)
{
    const int b = blockIdx.x;
    const int lane = threadIdx.x;

    const int is64 = warp_detect_is64((const int*)labels);
    const int il = warp_input_len(attention_mask, b);
    int ll = load_int(label_lengths, b, is64);
    ll = ll < 0 ? 0 : (ll > UU - 1 ? UU - 1 : ll);
    const int target_d = (il - 1) + ll;

    const float2* pD = g_probD + b * (DD * UP);
    const int u0 = lane * 4;                 // lanes 0..25 cover u = 0..103
    const bool lload = (u0 < UP);            // lanes 26+ never load (OOB guard)

    // 12-deep prefetch with NAMED registers.
    float4 pA0, pB0, pA1, pB1, pA2, pB2, pA3, pB3, pA4, pB4, pA5, pB5;
    float4 pA6, pB6, pA7, pB7, pA8, pB8, pA9, pB9, pA10, pB10, pA11, pB11;
#define PF_INIT(PA, PB, K)                                                    \
    if (lload) {                                                              \
        const float4* p_ = (const float4*)(pD + (K) * UP + u0);               \
        PA = p_[0]; PB = p_[1];                                               \
    } else { PA = make_float4(0,0,0,0); PB = make_float4(0,0,0,0); }
    PF_INIT(pA0, pB0, 0)  PF_INIT(pA1, pB1, 1)  PF_INIT(pA2, pB2, 2)
    PF_INIT(pA3, pB3, 3)  PF_INIT(pA4, pB4, 4)  PF_INIT(pA5, pB5, 5)
    PF_INIT(pA6, pB6, 6)  PF_INIT(pA7, pB7, 7)  PF_INIT(pA8, pB8, 8)
    PF_INIT(pA9, pB9, 9)  PF_INIT(pA10, pB10, 10) PF_INIT(pA11, pB11, 11)
#undef PF_INIT

    float a0 = 0.f, a1 = 0.f, a2 = 0.f, a3 = 0.f;   // alpha(d-1, u0..u0+3)

    // DCUR <= target_d is warp-uniform, so the shfl executes convergently.
#define ALPHA_STEP(PA, PB, DCUR)                                              \
    if ((DCUR) <= target_d) {                                                 \
        const float4 cA = PA, cB = PB;                                        \
        const int dn = (DCUR) + 12;                                           \
        if (lload && dn <= target_d) {                                        \
            const float4* pp = (const float4*)(pD + dn * UP + u0);            \
            PA = pp[0]; PB = pp[1];                                           \
        }                                                                     \
        const float left0 = __shfl_up_sync(0xffffffffu, a3, 1);               \
        const int t0 = (DCUR) - u0;                                           \
        const float n0 = stepcell(a0, left0, cA.x, cA.y, t0,     u0);         \
        const float n1 = stepcell(a1, a0,    cA.z, cA.w, t0 - 1, u0 + 1);     \
        const float n2 = stepcell(a2, a1,    cB.x, cB.y, t0 - 2, u0 + 2);     \
        const float n3 = stepcell(a3, a2,    cB.z, cB.w, t0 - 3, u0 + 3);     \
        a0 = n0; a1 = n1; a2 = n2; a3 = n3;                                   \
        if ((DCUR) == target_d && u0 <= ll && ll < u0 + 4) {                  \
            const float r = (ll == u0) ? n0 : (ll == u0 + 1) ? n1             \
                          : (ll == u0 + 2) ? n2 : n3;                         \
            const bool valid = (il > 0) && (ll > 0);                          \
            g_loss[b] = valid ? -r : 0.f;                                     \
            g_valid[b] = valid ? 1 : 0;                                       \
        }                                                                     \
    }

    for (int d = 0; d <= target_d; d += 12) {
        ALPHA_STEP(pA0, pB0, d)
        ALPHA_STEP(pA1, pB1, d + 1)
        ALPHA_STEP(pA2, pB2, d + 2)
        ALPHA_STEP(pA3, pB3, d + 3)
        ALPHA_STEP(pA4, pB4, d + 4)
        ALPHA_STEP(pA5, pB5, d + 5)
        ALPHA_STEP(pA6, pB6, d + 6)
        ALPHA_STEP(pA7, pB7, d + 7)
        ALPHA_STEP(pA8, pB8, d + 8)
        ALPHA_STEP(pA9, pB9, d + 9)
        ALPHA_STEP(pA10, pB10, d + 10)
        ALPHA_STEP(pA11, pB11, d + 11)
    }
#undef ALPHA_STEP

    // Fused mean reduction: last warp to arrive writes the scalar.
    if (lane == 0) {
        __threadfence();
        const unsigned tk = atomicAdd(&g_ticket, 1u);
        if (tk == BB - 1) {
            __threadfence();
            float s = 0.f;
            int nv = 0;
#pragma unroll
            for (int i = 0; i < BB; i++) { s += g_loss[i]; nv += g_valid[i]; }
            out[0] = s / (float)(nv > 0 ? nv : 1);
            g_ticket = 0;                  // reset for next graph replay
            __threadfence();
        }
    }
}

extern "C" void kernel_launch(void* const* d_in, const int* in_sizes, int n_in,
                              void* d_out, int out_size)
{
    const float* logits = (const float*)d_in[0];
    const void* labels = d_in[1];
    const void* label_lengths = d_in[2];
    const int* attention_mask = (const int*)d_in[3];
    float* out = (float*)d_out;

    lse_kernel<<<(NCELLS + 7) / 8, 256>>>(logits, labels, label_lengths, attention_mask);
    alpha_kernel<<<BB, 32>>>(labels, label_lengths, attention_mask, out);
}

// round 12
// speedup vs baseline: 3.9938x; 1.9932x over previous
#include <cuda_runtime.h>
#include <cuda_bf16.h>
#include <math.h>

// Problem constants: B=4, MAX_T=200, MAX_U=101, VOCAB=1024
#define BB 4
#define TT 200
#define UU 101
#define UP 104                    // padded U stride (16B alignment for float4)
#define VV 1024
#define DD (TT + UU - 1)          // 300 anti-diagonals
#define NCELLS (BB * TT * UU)     // 80800

// Scratch. Diagonal-major, padded, interleaved: g_probD[b][d*UP+u] = {blank_lp, label_lp}
__device__ __align__(16) float2 g_probD[BB * DD * UP];
__device__ float g_loss[BB];
__device__ int   g_valid[BB];
__device__ unsigned g_ticket;     // zero-init; last block resets after use

// ---------------------------------------------------------------------------
// Per-warp helpers (all 32 lanes participate). int64 labels < 1024 => every
// odd int32 word is 0 (P[false positive] ~ 1024^-64).
// ---------------------------------------------------------------------------
__device__ __forceinline__ int warp_detect_is64(const int* __restrict__ labels_i32)
{
    const int lane = threadIdx.x & 31;
    int ok = 1;
#pragma unroll
    for (int i = 1 + 2 * lane; i < 256; i += 64)
        ok &= (labels_i32[i] == 0);
    return __all_sync(0xffffffffu, ok);
}

__device__ __forceinline__ int warp_input_len(const int* __restrict__ attention_mask, int b)
{
    const int lane = threadIdx.x & 31;
    int acc = 0;
#pragma unroll
    for (int k = lane; k < TT; k += 32)
        acc += attention_mask[b * TT + k];
#pragma unroll
    for (int off = 16; off > 0; off >>= 1)
        acc += __shfl_xor_sync(0xffffffffu, acc, off);
    return acc < 1 ? 1 : (acc > TT ? TT : acc);
}

__device__ __forceinline__ int load_int(const void* p, int idx, int is64)
{
    return is64 ? (int)((const long long*)p)[idx] : ((const int*)p)[idx];
}

// ---------------------------------------------------------------------------
// Kernel 1: streaming logsumexp over V=1024 per live cell; one warp/cell.
// Logits loaded with __ldcs (evict-first; zero reuse). Dead cells exit before
// any logits loads. Writes diagonal-major padded layout at CONSUMER position:
//   blank of (t,u)    -> g_probD[b][(t+u)*UP + u].x
//   label_lp of (t,u) -> g_probD[b][(t+u+1)*UP + (u+1)].y
// ---------------------------------------------------------------------------
__global__ void __launch_bounds__(256)
lse_kernel(const float* __restrict__ logits,
           const void* __restrict__ labels,
           const void* __restrict__ label_lengths,
           const int* __restrict__ attention_mask)
{
    const int warp = threadIdx.x >> 5;
    const int lane = threadIdx.x & 31;
    const int cell = blockIdx.x * 8 + warp;
    if (cell >= NCELLS) return;

    const int b = cell / (TT * UU);
    const int rem = cell - b * (TT * UU);
    const int t = rem / UU;
    const int u = rem - t * UU;

    const int is64 = warp_detect_is64((const int*)labels);
    int ll = load_int(label_lengths, b, is64);
    ll = ll < 0 ? 0 : (ll > UU - 1 ? UU - 1 : ll);
    const int il = warp_input_len(attention_mask, b);
    if (u > ll || t >= il) return;          // dead cell: skip all logits loads

    const float* base = logits + (size_t)cell * VV;
    const float4* p = (const float4*)base;

    float s = 0.f;
    float first = 0.f;   // lane 0, i=0, .x == blank logit
#pragma unroll
    for (int i = 0; i < 8; i++) {
        float4 v = __ldcs(p + i * 32 + lane);      // streaming: don't pollute L2
        if (i == 0) first = v.x;
        s += __expf(v.x) + __expf(v.y) + __expf(v.z) + __expf(v.w);
    }
#pragma unroll
    for (int off = 16; off > 0; off >>= 1)
        s += __shfl_xor_sync(0xffffffffu, s, off);

    const float lse = __logf(s);

    if (lane == 0) {
        float* pd = (float*)g_probD;
        const int base_b = b * (DD * UP);
        pd[2 * (base_b + (t + u) * UP + u)] = first - lse;          // .x blank
        if (u < ll) {
            int lab = load_int(labels, b * (UU - 1) + u, is64);
            lab = lab < 0 ? 0 : (lab > VV - 1 ? VV - 1 : lab);
            const float lab_logit = __ldcs(base + lab);
            pd[2 * (base_b + (t + u + 1) * UP + (u + 1)) + 1] = lab_logit - lse;  // .y
        }
    }
}

// ---------------------------------------------------------------------------
// Kernel 2: alpha wavefront, ONE WARP per sample, 4 u-values per lane.
// Inner loop fully BRANCH-FREE per lane:
//   - all 32 lanes load; lanes 26-31 clamp to uL=100 (EVEN -> float4-aligned,
//     in-bounds since UP=104); their garbage only moves upward via shfl_up;
//   - prefetch diagonal index clamped (SEL) instead of guarded;
//   - stepcell uses selects only; result extracted AFTER the loop via shfl;
//   - d-loop split into unguarded 12-step blocks + uniform-guarded tail.
// ---------------------------------------------------------------------------
__device__ __forceinline__ float stepcell(float top, float left,
                                          float blank, float label,
                                          int t, int u)
{
    const float viaB = top + blank;
    const float viaL = left + label;
    const float mx = fmaxf(viaB, viaL);
    const float mn = fminf(viaB, viaL);
    const float both = mx + __logf(1.f + __expf(mn - mx));
    float r = (t == 0) ? viaL : both;              // label-only top row
    r = (u == 0) ? ((t == 0) ? blank : viaB) : r;  // blank-only column / origin
    return r;
}

__global__ void __launch_bounds__(32)
alpha_kernel(const void* __restrict__ labels,
             const void* __restrict__ label_lengths,
             const int* __restrict__ attention_mask,
             float* __restrict__ out)
{
    const int b = blockIdx.x;
    const int lane = threadIdx.x;

    const int is64 = warp_detect_is64((const int*)labels);
    const int il = warp_input_len(attention_mask, b);
    int ll = load_int(label_lengths, b, is64);
    ll = ll < 0 ? 0 : (ll > UU - 1 ? UU - 1 : ll);
    const int target_d = (il - 1) + ll;

    const float2* pD = g_probD + b * (DD * UP);
    const int u0 = lane * 4;                 // logical u base for this lane
    const int uL = (u0 <= 100) ? u0 : 100;   // load base: EVEN (16B-aligned), <= UP-4

    // 12-deep prefetch with NAMED registers.
    float4 pA0, pB0, pA1, pB1, pA2, pB2, pA3, pB3, pA4, pB4, pA5, pB5;
    float4 pA6, pB6, pA7, pB7, pA8, pB8, pA9, pB9, pA10, pB10, pA11, pB11;
#define PF_LOAD(PA, PB, K)                                                    \
    {                                                                         \
        const float4* p_ = (const float4*)(pD + (K) * UP + uL);               \
        PA = p_[0]; PB = p_[1];                                               \
    }
    PF_LOAD(pA0, pB0, 0)  PF_LOAD(pA1, pB1, 1)  PF_LOAD(pA2, pB2, 2)
    PF_LOAD(pA3, pB3, 3)  PF_LOAD(pA4, pB4, 4)  PF_LOAD(pA5, pB5, 5)
    PF_LOAD(pA6, pB6, 6)  PF_LOAD(pA7, pB7, 7)  PF_LOAD(pA8, pB8, 8)
    PF_LOAD(pA9, pB9, 9)  PF_LOAD(pA10, pB10, 10) PF_LOAD(pA11, pB11, 11)
#undef PF_LOAD

    float a0 = 0.f, a1 = 0.f, a2 = 0.f, a3 = 0.f;   // alpha(d-1, u0..u0+3)

    // One step: clamped prefetch + shfl + 4 independent cells (select-only).
#define ALPHA_STEP(PA, PB, DCUR)                                              \
    {                                                                         \
        const float4 cA = PA, cB = PB;                                        \
        const int dn = (DCUR) + 12;                                           \
        const int dnc = dn < DD ? dn : DD - 1;                                \
        const float4* pp = (const float4*)(pD + dnc * UP + uL);               \
        PA = pp[0]; PB = pp[1];                                               \
        const float left0 = __shfl_up_sync(0xffffffffu, a3, 1);               \
        const int t0 = (DCUR) - u0;                                           \
        const float n0 = stepcell(a0, left0, cA.x, cA.y, t0,     u0);         \
        const float n1 = stepcell(a1, a0,    cA.z, cA.w, t0 - 1, u0 + 1);     \
        const float n2 = stepcell(a2, a1,    cB.x, cB.y, t0 - 2, u0 + 2);     \
        const float n3 = stepcell(a3, a2,    cB.z, cB.w, t0 - 3, u0 + 3);     \
        a0 = n0; a1 = n1; a2 = n2; a3 = n3;                                   \
    }

    int d = 0;
    for (; d + 11 <= target_d; d += 12) {    // full blocks: no per-step guards
        ALPHA_STEP(pA0, pB0, d)
        ALPHA_STEP(pA1, pB1, d + 1)
        ALPHA_STEP(pA2, pB2, d + 2)
        ALPHA_STEP(pA3, pB3, d + 3)
        ALPHA_STEP(pA4, pB4, d + 4)
        ALPHA_STEP(pA5, pB5, d + 5)
        ALPHA_STEP(pA6, pB6, d + 6)
        ALPHA_STEP(pA7, pB7, d + 7)
        ALPHA_STEP(pA8, pB8, d + 8)
        ALPHA_STEP(pA9, pB9, d + 9)
        ALPHA_STEP(pA10, pB10, d + 10)
        ALPHA_STEP(pA11, pB11, d + 11)
    }
    // tail: warp-uniform guards (all guard operands warp-uniform)
    if (d     <= target_d) ALPHA_STEP(pA0, pB0, d)
    if (d + 1 <= target_d) ALPHA_STEP(pA1, pB1, d + 1)
    if (d + 2 <= target_d) ALPHA_STEP(pA2, pB2, d + 2)
    if (d + 3 <= target_d) ALPHA_STEP(pA3, pB3, d + 3)
    if (d + 4 <= target_d) ALPHA_STEP(pA4, pB4, d + 4)
    if (d + 5 <= target_d) ALPHA_STEP(pA5, pB5, d + 5)
    if (d + 6 <= target_d) ALPHA_STEP(pA6, pB6, d + 6)
    if (d + 7 <= target_d) ALPHA_STEP(pA7, pB7, d + 7)
    if (d + 8 <= target_d) ALPHA_STEP(pA8, pB8, d + 8)
    if (d + 9 <= target_d) ALPHA_STEP(pA9, pB9, d + 9)
    if (d + 10 <= target_d) ALPHA_STEP(pA10, pB10, d + 10)
#undef ALPHA_STEP

    // Result extraction: alpha(target_d, ll) lives in lane ll>>2, slot ll&3.
    const int src_lane = ll >> 2;
    const int sub = ll & 3;
    const float r0 = __shfl_sync(0xffffffffu, a0, src_lane);
    const float r1 = __shfl_sync(0xffffffffu, a1, src_lane);
    const float r2 = __shfl_sync(0xffffffffu, a2, src_lane);
    const float r3 = __shfl_sync(0xffffffffu, a3, src_lane);
    const float r = (sub == 0) ? r0 : (sub == 1) ? r1 : (sub == 2) ? r2 : r3;

    if (lane == 0) {
        const bool valid = (il > 0) && (ll > 0);
        g_loss[b] = valid ? -r : 0.f;
        g_valid[b] = valid ? 1 : 0;

        // Fused mean reduction: last warp to arrive writes the scalar.
        __threadfence();
        const unsigned tk = atomicAdd(&g_ticket, 1u);
        if (tk == BB - 1) {
            __threadfence();
            float s = 0.f;
            int nv = 0;
#pragma unroll
            for (int i = 0; i < BB; i++) { s += g_loss[i]; nv += g_valid[i]; }
            out[0] = s / (float)(nv > 0 ? nv : 1);
            g_ticket = 0;                  // reset for next graph replay
            __threadfence();
        }
    }
}

extern "C" void kernel_launch(void* const* d_in, const int* in_sizes, int n_in,
                              void* d_out, int out_size)
{
    const float* logits = (const float*)d_in[0];
    const void* labels = d_in[1];
    const void* label_lengths = d_in[2];
    const int* attention_mask = (const int*)d_in[3];
    float* out = (float*)d_out;

    lse_kernel<<<(NCELLS + 7) / 8, 256>>>(logits, labels, label_lengths, attention_mask);
    alpha_kernel<<<BB, 32>>>(labels, label_lengths, attention_mask, out);
}